// round 1
// baseline (speedup 1.0000x reference)
#include <cuda_runtime.h>
#include <math.h>

// Problem constants
#define BQ 8
#define TT 2048
#define DD 512
#define SDIM 256
#define ODIM 64
#define MM (BQ*TT)          // 16384 rows
#define N1 768              // padded 704 (gate 0-255 | in 256-511 | v 512-575 | k 576-639 | q 640-703)
#define KC2 320             // states(256) + bind(64)
#define NCH 64              // scan chunks of 32
#define CHK 32
#define CB 64               // binding chunk
#define NCB 32

// ---------------- device scratch (no runtime allocation) ----------------
__device__ float g_W1[DD*N1];
__device__ float g_b1[N1];
__device__ float g_Z[(size_t)MM*N1];
__device__ float g_W2[KC2*DD];
__device__ float g_b2[DD];
__device__ float g_A2[(size_t)MM*KC2];
__device__ float g_Y[(size_t)MM*DD];
__device__ float g_sumA[BQ*NCH*SDIM];
__device__ float g_sumB[BQ*NCH*SDIM];
__device__ float g_hpr[BQ*NCH*SDIM];
__device__ float g_Mc[(size_t)BQ*NCB*ODIM*ODIM];
__device__ float g_Sc[(size_t)BQ*NCB*ODIM*ODIM];
__device__ float g_pw[65*ODIM];

__device__ __forceinline__ float sigm(float z){ return 1.0f/(1.0f+expf(-z)); }

// ---------------- prep kernels ----------------
__global__ void pack_w1(const float* __restrict__ gW, const float* __restrict__ gb,
                        const float* __restrict__ iW, const float* __restrict__ ib,
                        const float* __restrict__ vW, const float* __restrict__ vb,
                        const float* __restrict__ kW, const float* __restrict__ kb,
                        const float* __restrict__ qW, const float* __restrict__ qb)
{
    int idx = blockIdx.x*256 + threadIdx.x;
    if (idx < DD*N1) {
        int d = idx / N1, n = idx % N1;
        float w = 0.f;
        if      (n < 256) w = gW[d*256 + n];
        else if (n < 512) w = iW[d*256 + (n-256)];
        else if (n < 576) w = vW[d*64 + (n-512)];
        else if (n < 640) w = kW[d*64 + (n-576)];
        else if (n < 704) w = qW[d*64 + (n-640)];
        g_W1[idx] = w;
    }
    if (idx < N1) {
        float b = 0.f;
        if      (idx < 256) b = gb[idx];
        else if (idx < 512) b = ib[idx-256];
        else if (idx < 576) b = vb[idx-512];
        else if (idx < 640) b = kb[idx-576];
        else if (idx < 704) b = qb[idx-640];
        g_b1[idx] = b;
    }
}

__global__ void pack_w2(const float* __restrict__ oW, const float* __restrict__ ob,
                        const float* __restrict__ pW, const float* __restrict__ pb)
{
    int idx = blockIdx.x*256 + threadIdx.x;
    if (idx < KC2*DD) {
        int r = idx / DD, c = idx % DD;
        g_W2[idx] = (r < 256) ? oW[r*DD + c] : pW[(r-256)*DD + c];
    }
    if (idx < DD) g_b2[idx] = ob[idx] + pb[idx];
}

__global__ void pw_kernel(const float* __restrict__ op_decay)
{
    int i = threadIdx.x;
    if (i < ODIM) {
        float d = sigm(op_decay[i]);
        float p = 1.f;
        for (int e = 0; e <= 64; e++) { g_pw[e*ODIM + i] = p; p *= d; }
    }
}

// ---------------- FFMA GEMM: C[M,N] = A[M,K] @ B[K,N] + bias (+ addsrc) ----------------
// 128x128 tile, BK=8, 256 threads, 8x8 per thread
__global__ void __launch_bounds__(256,2) sgemm_bias(
    const float* __restrict__ A, int lda,
    const float* __restrict__ Bw, int ldb,
    const float* __restrict__ bias,
    const float* __restrict__ addsrc, int ldadd,
    float* __restrict__ C, int ldc, int K)
{
    __shared__ float As[8][132];
    __shared__ float Bs[8][128];
    int tid = threadIdx.x;
    int tr = tid >> 4, tc = tid & 15;
    const float* Ab = A + (size_t)blockIdx.y*128*lda;
    const float* Bb = Bw + blockIdx.x*128;
    int arow = tid >> 1, acol = (tid & 1) * 4;
    int brow = tid >> 5, bcol = (tid & 31) * 4;
    float acc[8][8] = {};

    for (int k0 = 0; k0 < K; k0 += 8) {
        float4 av = *(const float4*)(Ab + (size_t)arow*lda + k0 + acol);
        float4 bv = *(const float4*)(Bb + (size_t)(k0+brow)*ldb + bcol);
        __syncthreads();
        As[acol+0][arow] = av.x; As[acol+1][arow] = av.y;
        As[acol+2][arow] = av.z; As[acol+3][arow] = av.w;
        *(float4*)&Bs[brow][bcol] = bv;
        __syncthreads();
        #pragma unroll
        for (int k = 0; k < 8; k++) {
            float a[8], bb[8];
            *(float4*)&a[0]  = *(const float4*)&As[k][tr*8];
            *(float4*)&a[4]  = *(const float4*)&As[k][tr*8+4];
            *(float4*)&bb[0] = *(const float4*)&Bs[k][tc*8];
            *(float4*)&bb[4] = *(const float4*)&Bs[k][tc*8+4];
            #pragma unroll
            for (int i = 0; i < 8; i++)
                #pragma unroll
                for (int j = 0; j < 8; j++)
                    acc[i][j] += a[i]*bb[j];
        }
    }
    int nbase = blockIdx.x*128 + tc*8;
    float bv0[8];
    #pragma unroll
    for (int j = 0; j < 8; j++) bv0[j] = bias[nbase+j];
    #pragma unroll
    for (int i = 0; i < 8; i++) {
        size_t row = (size_t)blockIdx.y*128 + tr*8 + i;
        float add[8] = {0,0,0,0,0,0,0,0};
        if (addsrc) {
            const float* ar = addsrc + row*(size_t)ldadd + nbase;
            float4 a0 = *(const float4*)ar;
            float4 a1 = *(const float4*)(ar+4);
            add[0]=a0.x; add[1]=a0.y; add[2]=a0.z; add[3]=a0.w;
            add[4]=a1.x; add[5]=a1.y; add[6]=a1.z; add[7]=a1.w;
        }
        float* crow = C + row*(size_t)ldc + nbase;
        float4 r0 = make_float4(acc[i][0]+bv0[0]+add[0], acc[i][1]+bv0[1]+add[1],
                                acc[i][2]+bv0[2]+add[2], acc[i][3]+bv0[3]+add[3]);
        float4 r1 = make_float4(acc[i][4]+bv0[4]+add[4], acc[i][5]+bv0[5]+add[5],
                                acc[i][6]+bv0[6]+add[6], acc[i][7]+bv0[7]+add[7]);
        *(float4*)crow = r0;
        *(float4*)(crow+4) = r1;
    }
}

// ---------------- gated scan ----------------
// K2: per-(b,chunk,sd) compute (cum_a_last, cum_wb_last) with reference clamp semantics
__global__ void scan_summ()
{
    int bc = blockIdx.x;               // 0..511
    int b = bc >> 6, c = bc & 63;
    int sd = threadIdx.x;
    size_t base = ((size_t)(b*TT + c*CHK))*N1 + sd;
    float ca = 1.f, wb = 0.f;
    for (int k = 0; k < CHK; k++) {
        float zg = g_Z[base + (size_t)k*N1];
        float zi = g_Z[base + (size_t)k*N1 + SDIM];
        float a = sigm(zg);
        float bb = (1.f - a)*zi;
        ca *= a;
        wb += bb / fmaxf(ca, 1e-8f);
    }
    int idx = bc*SDIM + sd;
    g_sumA[idx] = ca; g_sumB[idx] = wb;
}

// K3: carry scan over 64 chunks per (b,sd) lane
__global__ void scan_carry()
{
    int b = blockIdx.x;
    int sd = threadIdx.x;
    float h = 0.f;
    for (int c = 0; c < NCH; c++) {
        int idx = (b*NCH + c)*SDIM + sd;
        g_hpr[idx] = h;
        h = g_sumA[idx]*(h + g_sumB[idx]);
    }
}

// K4: expand states, write into A2 cols [0,256)
__global__ void scan_states()
{
    int bc = blockIdx.x;
    int b = bc >> 6, c = bc & 63;
    int sd = threadIdx.x;
    size_t zb = ((size_t)(b*TT + c*CHK))*N1 + sd;
    size_t ob = ((size_t)(b*TT + c*CHK))*KC2 + sd;
    float h = g_hpr[bc*SDIM + sd];
    float ca = 1.f, wb = 0.f;
    for (int k = 0; k < CHK; k++) {
        float zg = g_Z[zb + (size_t)k*N1];
        float zi = g_Z[zb + (size_t)k*N1 + SDIM];
        float a = sigm(zg);
        float bb = (1.f - a)*zi;
        ca *= a;
        wb += bb / fmaxf(ca, 1e-8f);
        g_A2[ob + (size_t)k*KC2] = ca*(h + wb);
    }
}

// ---------------- binding scan ----------------
// K5a: per-(b,chunk) M[i][l] = sum_j dec[i]^(63-j) v_j[i] k_j[l]
__global__ void bind_chunksum()
{
    __shared__ float Vs[CB*ODIM];
    __shared__ float Ks[CB*ODIM];
    int b = blockIdx.x >> 5, c = blockIdx.x & 31;
    int tid = threadIdx.x;
    int j = tid >> 2, q0 = (tid & 3)*16;
    size_t zrow = ((size_t)(b*TT + c*CB + j))*N1;
    #pragma unroll
    for (int u = 0; u < 4; u++) {
        float4 vv = *(const float4*)&g_Z[zrow + 512 + q0 + u*4];
        float4 pp = *(const float4*)&g_pw[(63-j)*ODIM + q0 + u*4];
        vv.x *= pp.x; vv.y *= pp.y; vv.z *= pp.z; vv.w *= pp.w;
        *(float4*)&Vs[j*ODIM + q0 + u*4] = vv;
        float4 kk = *(const float4*)&g_Z[zrow + 576 + q0 + u*4];
        *(float4*)&Ks[j*ODIM + q0 + u*4] = kk;
    }
    __syncthreads();
    int i = tid >> 2, l0 = (tid & 3)*16;
    float acc[16] = {};
    for (int jj = 0; jj < CB; jj++) {
        float vv = Vs[jj*ODIM + i];
        #pragma unroll
        for (int u = 0; u < 16; u += 4) {
            float4 k4 = *(const float4*)&Ks[jj*ODIM + l0 + u];
            acc[u+0] += vv*k4.x; acc[u+1] += vv*k4.y;
            acc[u+2] += vv*k4.z; acc[u+3] += vv*k4.w;
        }
    }
    size_t mb = ((size_t)(b*NCB + c))*ODIM*ODIM + i*ODIM + l0;
    #pragma unroll
    for (int u = 0; u < 16; u += 4)
        *(float4*)&g_Mc[mb + u] = make_float4(acc[u], acc[u+1], acc[u+2], acc[u+3]);
}

// K5b: S carry across 32 chunks
__global__ void bind_carry()
{
    int gid = blockIdx.x*blockDim.x + threadIdx.x;   // 32768 lanes
    int b = gid >> 12, e = gid & 4095, i = e >> 6;
    float p64 = g_pw[64*ODIM + i];
    float s = 0.f;
    size_t base = (size_t)b*NCB*4096 + e;
    for (int c = 0; c < NCB; c++) {
        g_Sc[base + (size_t)c*4096] = s;
        s = p64*s + g_Mc[base + (size_t)c*4096];
    }
}

// K5c: per-chunk binding outputs -> A2 cols [256,320)
__global__ void bind_out()
{
    extern __shared__ float sm[];
    float* Qs  = sm;            // [64][65]  Q[t][l]
    float* KT  = sm + 4160;     // [64][64]  K^T[l][j] -> later Cq[t][i]
    float* SV  = sm + 8256;     // [64][64]  S^T[l][i] -> later V[j][i]
    float* As  = sm + 12352;    // [64][65]  A[t][j]
    float* pws = sm + 16512;    // [65][64]
    int b = blockIdx.x >> 5, c = blockIdx.x & 31;
    int tid = threadIdx.x;
    int t = tid >> 2, q0 = (tid & 3)*16;
    size_t zrow = ((size_t)(b*TT + c*CB + t))*N1;
    size_t srow = ((size_t)(b*NCB + c))*4096 + t*ODIM;
    #pragma unroll
    for (int u = 0; u < 4; u++) {
        float4 qv = *(const float4*)&g_Z[zrow + 640 + q0 + u*4];
        Qs[t*65 + q0+u*4+0] = qv.x; Qs[t*65 + q0+u*4+1] = qv.y;
        Qs[t*65 + q0+u*4+2] = qv.z; Qs[t*65 + q0+u*4+3] = qv.w;
        float4 kv = *(const float4*)&g_Z[zrow + 576 + q0 + u*4];     // t plays "j"
        KT[(q0+u*4+0)*ODIM + t] = kv.x; KT[(q0+u*4+1)*ODIM + t] = kv.y;
        KT[(q0+u*4+2)*ODIM + t] = kv.z; KT[(q0+u*4+3)*ODIM + t] = kv.w;
        float4 sv = *(const float4*)&g_Sc[srow + q0 + u*4];          // t plays "i"
        SV[(q0+u*4+0)*ODIM + t] = sv.x; SV[(q0+u*4+1)*ODIM + t] = sv.y;
        SV[(q0+u*4+2)*ODIM + t] = sv.z; SV[(q0+u*4+3)*ODIM + t] = sv.w;
    }
    for (int idx = tid; idx < 65*ODIM; idx += 256) pws[idx] = g_pw[idx];
    __syncthreads();

    float accA[16] = {}, accC[16] = {};
    for (int l = 0; l < ODIM; l++) {
        float q = Qs[t*65 + l];
        #pragma unroll
        for (int u = 0; u < 16; u += 4) {
            float4 k4 = *(const float4*)&KT[l*ODIM + q0 + u];
            float4 s4 = *(const float4*)&SV[l*ODIM + q0 + u];
            accA[u+0] += q*k4.x; accA[u+1] += q*k4.y; accA[u+2] += q*k4.z; accA[u+3] += q*k4.w;
            accC[u+0] += q*s4.x; accC[u+1] += q*s4.y; accC[u+2] += q*s4.z; accC[u+3] += q*s4.w;
        }
    }
    __syncthreads();
    #pragma unroll
    for (int u = 0; u < 16; u++) As[t*65 + q0 + u] = accA[u];
    #pragma unroll
    for (int u = 0; u < 16; u += 4)
        *(float4*)&KT[t*ODIM + q0 + u] = make_float4(accC[u], accC[u+1], accC[u+2], accC[u+3]);
    #pragma unroll
    for (int u = 0; u < 4; u++) {
        float4 vv = *(const float4*)&g_Z[zrow + 512 + q0 + u*4];     // t plays "j"
        *(float4*)&SV[t*ODIM + q0 + u*4] = vv;
    }
    __syncthreads();

    float o[16];
    #pragma unroll
    for (int u = 0; u < 16; u++)
        o[u] = pws[(t+1)*ODIM + q0 + u] * KT[t*ODIM + q0 + u];
    for (int j = 0; j <= t; j++) {
        float a = As[t*65 + j];
        int d = t - j;
        #pragma unroll
        for (int u = 0; u < 16; u += 4) {
            float4 p4 = *(const float4*)&pws[d*ODIM + q0 + u];
            float4 v4 = *(const float4*)&SV[j*ODIM + q0 + u];
            o[u+0] += a*p4.x*v4.x; o[u+1] += a*p4.y*v4.y;
            o[u+2] += a*p4.z*v4.z; o[u+3] += a*p4.w*v4.w;
        }
    }
    size_t orow = ((size_t)(b*TT + c*CB + t))*KC2 + SDIM + q0;
    #pragma unroll
    for (int u = 0; u < 16; u += 4)
        *(float4*)&g_A2[orow + u] = make_float4(o[u], o[u+1], o[u+2], o[u+3]);
}

// ---------------- layernorm: warp per row ----------------
__global__ void ln_kernel(const float* __restrict__ lng, const float* __restrict__ lnb,
                          float* __restrict__ out)
{
    int row = blockIdx.x*8 + (threadIdx.x >> 5);
    int lane = threadIdx.x & 31;
    const float4* y4 = (const float4*)(g_Y + (size_t)row*DD);
    float4 v[4];
    float s = 0.f, s2 = 0.f;
    #pragma unroll
    for (int u = 0; u < 4; u++) {
        v[u] = y4[lane + u*32];
        s  += v[u].x + v[u].y + v[u].z + v[u].w;
        s2 += v[u].x*v[u].x + v[u].y*v[u].y + v[u].z*v[u].z + v[u].w*v[u].w;
    }
    #pragma unroll
    for (int off = 16; off; off >>= 1) {
        s  += __shfl_xor_sync(0xffffffffu, s,  off);
        s2 += __shfl_xor_sync(0xffffffffu, s2, off);
    }
    float mu  = s * (1.f/512.f);
    float var = s2 * (1.f/512.f) - mu*mu;
    float inv = rsqrtf(var + 1e-5f);
    float4* o4 = (float4*)(out + (size_t)row*DD);
    const float4* g4 = (const float4*)lng;
    const float4* b4 = (const float4*)lnb;
    #pragma unroll
    for (int u = 0; u < 4; u++) {
        float4 gg = g4[lane + u*32];
        float4 bb = b4[lane + u*32];
        float4 r;
        r.x = (v[u].x - mu)*inv*gg.x + bb.x;
        r.y = (v[u].y - mu)*inv*gg.y + bb.y;
        r.z = (v[u].z - mu)*inv*gg.z + bb.z;
        r.w = (v[u].w - mu)*inv*gg.w + bb.w;
        o4[lane + u*32] = r;
    }
}

// ---------------- host launch ----------------
extern "C" void kernel_launch(void* const* d_in, const int* in_sizes, int n_in,
                              void* d_out, int out_size)
{
    const float* x       = (const float*)d_in[0];
    const float* gate_W  = (const float*)d_in[1];
    const float* gate_b  = (const float*)d_in[2];
    const float* in_W    = (const float*)d_in[3];
    const float* in_b    = (const float*)d_in[4];
    const float* out_W   = (const float*)d_in[5];
    const float* out_b   = (const float*)d_in[6];
    const float* opv_W   = (const float*)d_in[7];
    const float* opv_b   = (const float*)d_in[8];
    const float* opk_W   = (const float*)d_in[9];
    const float* opk_b   = (const float*)d_in[10];
    const float* opq_W   = (const float*)d_in[11];
    const float* opq_b   = (const float*)d_in[12];
    const float* op_decay= (const float*)d_in[13];
    const float* opout_W = (const float*)d_in[14];
    const float* opout_b = (const float*)d_in[15];
    const float* ln_g    = (const float*)d_in[16];
    const float* ln_b    = (const float*)d_in[17];
    float* out = (float*)d_out;

    void *pW1, *pb1, *pZ, *pW2, *pb2, *pA2, *pY;
    cudaGetSymbolAddress(&pW1, g_W1);
    cudaGetSymbolAddress(&pb1, g_b1);
    cudaGetSymbolAddress(&pZ,  g_Z);
    cudaGetSymbolAddress(&pW2, g_W2);
    cudaGetSymbolAddress(&pb2, g_b2);
    cudaGetSymbolAddress(&pA2, g_A2);
    cudaGetSymbolAddress(&pY,  g_Y);

    cudaFuncSetAttribute(bind_out, cudaFuncAttributeMaxDynamicSharedMemorySize, 20672*4);

    // prep
    pack_w1<<<(DD*N1 + 255)/256, 256>>>(gate_W, gate_b, in_W, in_b,
                                        opv_W, opv_b, opk_W, opk_b, opq_W, opq_b);
    pack_w2<<<(KC2*DD + 255)/256, 256>>>(out_W, out_b, opout_W, opout_b);
    pw_kernel<<<1, 64>>>(op_decay);

    // GEMM-1: Z = x @ W1 + b1
    sgemm_bias<<<dim3(N1/128, MM/128), 256>>>(
        x, DD, (const float*)pW1, N1, (const float*)pb1,
        nullptr, 0, (float*)pZ, N1, DD);

    // gated scan
    scan_summ<<<BQ*NCH, SDIM>>>();
    scan_carry<<<BQ, SDIM>>>();
    scan_states<<<BQ*NCH, SDIM>>>();

    // binding scan
    bind_chunksum<<<BQ*NCB, 256>>>();
    bind_carry<<<BQ*NCB*16/32, 256>>>();      // 32768 lanes / 256
    bind_out<<<BQ*NCB, 256, 20672*4>>>();

    // GEMM-2: Y = A2 @ W2 + b2 + x
    sgemm_bias<<<dim3(DD/128, MM/128), 256>>>(
        (const float*)pA2, KC2, (const float*)pW2, DD, (const float*)pb2,
        x, DD, (float*)pY, DD, KC2);

    // layernorm -> out
    ln_kernel<<<MM/8, 256>>>(ln_g, ln_b, out);
}

// round 2
// speedup vs baseline: 1.8285x; 1.8285x over previous
#include <cuda_runtime.h>
#include <math.h>

// Problem constants
#define BQ 8
#define TT 2048
#define DD 512
#define SDIM 256
#define ODIM 64
#define MM (BQ*TT)          // 16384 rows
#define N1 768              // padded 704 (gate 0-255 | in 256-511 | v 512-575 | k 576-639 | q 640-703)
#define KC2 320             // states(256) + bind(64)
#define NCH 64              // scan chunks of 32
#define CHK 32
#define CB 64               // binding chunk
#define NCB 32

// ---------------- device scratch (no runtime allocation) ----------------
__device__ float g_W1[DD*N1];
__device__ float g_b1[N1];
__device__ float g_Z[(size_t)MM*N1];
__device__ float g_W2[KC2*DD];
__device__ float g_b2[DD];
__device__ float g_A2[(size_t)MM*KC2];
__device__ float g_Y[(size_t)MM*DD];
__device__ float g_sumA[BQ*NCH*SDIM];
__device__ float g_sumB[BQ*NCH*SDIM];
__device__ float g_hpr[BQ*NCH*SDIM];
__device__ float g_Mc[(size_t)BQ*NCB*ODIM*ODIM];
__device__ float g_Sc[(size_t)BQ*NCB*ODIM*ODIM];
__device__ float g_pw[65*ODIM];

__device__ __forceinline__ float sigm(float z){ return 1.0f/(1.0f+expf(-z)); }

// ---------------- prep kernels ----------------
__global__ void pack_w1(const float* __restrict__ gW, const float* __restrict__ gb,
                        const float* __restrict__ iW, const float* __restrict__ ib,
                        const float* __restrict__ vW, const float* __restrict__ vb,
                        const float* __restrict__ kW, const float* __restrict__ kb,
                        const float* __restrict__ qW, const float* __restrict__ qb)
{
    int idx = blockIdx.x*256 + threadIdx.x;
    if (idx < DD*N1) {
        int d = idx / N1, n = idx % N1;
        float w = 0.f;
        if      (n < 256) w = gW[d*256 + n];
        else if (n < 512) w = iW[d*256 + (n-256)];
        else if (n < 576) w = vW[d*64 + (n-512)];
        else if (n < 640) w = kW[d*64 + (n-576)];
        else if (n < 704) w = qW[d*64 + (n-640)];
        g_W1[idx] = w;
    }
    if (idx < N1) {
        float b = 0.f;
        if      (idx < 256) b = gb[idx];
        else if (idx < 512) b = ib[idx-256];
        else if (idx < 576) b = vb[idx-512];
        else if (idx < 640) b = kb[idx-576];
        else if (idx < 704) b = qb[idx-640];
        g_b1[idx] = b;
    }
}

__global__ void pack_w2(const float* __restrict__ oW, const float* __restrict__ ob,
                        const float* __restrict__ pW, const float* __restrict__ pb)
{
    int idx = blockIdx.x*256 + threadIdx.x;
    if (idx < KC2*DD) {
        int r = idx / DD, c = idx % DD;
        g_W2[idx] = (r < 256) ? oW[r*DD + c] : pW[(r-256)*DD + c];
    }
    if (idx < DD) g_b2[idx] = ob[idx] + pb[idx];
}

__global__ void pw_kernel(const float* __restrict__ op_decay)
{
    int i = threadIdx.x;
    if (i < ODIM) {
        float d = sigm(op_decay[i]);
        float p = 1.f;
        for (int e = 0; e <= 64; e++) { g_pw[e*ODIM + i] = p; p *= d; }
    }
}

// ---------------- tf32 tensor-core GEMM ----------------
// C[M,N] = A[M,K] @ B[K,N] + bias (+ addsrc). 128x128x16 tile, 256 thr, 8 warps.
// Warp tile 64x32 via mma.sync.m16n8k8 tf32.
#define ASTRIDE 20
#define BSTRIDE 136

__device__ __forceinline__ unsigned f2tf(float x){
    unsigned r; asm("cvt.rna.tf32.f32 %0, %1;" : "=r"(r) : "f"(x)); return r;
}
__device__ __forceinline__ void mma_tf32(float* c, const unsigned* a, const unsigned* b){
    asm volatile(
      "mma.sync.aligned.m16n8k8.row.col.f32.tf32.tf32.f32 "
      "{%0,%1,%2,%3}, {%4,%5,%6,%7}, {%8,%9}, {%0,%1,%2,%3};\n"
      : "+f"(c[0]), "+f"(c[1]), "+f"(c[2]), "+f"(c[3])
      : "r"(a[0]), "r"(a[1]), "r"(a[2]), "r"(a[3]), "r"(b[0]), "r"(b[1]));
}
__device__ __forceinline__ void cpa16(void* dst, const void* src){
    unsigned d = (unsigned)__cvta_generic_to_shared(dst);
    asm volatile("cp.async.cg.shared.global [%0], [%1], 16;" :: "r"(d), "l"(src));
}

__global__ void __launch_bounds__(256) gemm_tf32(
    const float* __restrict__ A, int lda,
    const float* __restrict__ Bw, int ldb,
    const float* __restrict__ bias,
    const float* __restrict__ addsrc, int ldadd,
    float* __restrict__ C, int ldc, int K)
{
    __shared__ float As[2][128][ASTRIDE];   // [m][k] padded
    __shared__ float Bs[2][16][BSTRIDE];    // [k][n] padded

    int tid  = threadIdx.x;
    int lane = tid & 31, warp = tid >> 5;
    int wm = (warp >> 2) * 64;      // warp m offset (0/64)
    int wn = (warp & 3) * 32;       // warp n offset (0..96)
    int lr = lane >> 2;             // 0..7
    int lc = lane & 3;              // 0..3

    size_t rowBase = (size_t)blockIdx.y * 128;
    int colBase = blockIdx.x * 128;

    // load indices (512 16B-chunks per tile, 2 per thread)
    int ac0 = tid, ac1 = tid + 256;

    float acc[4][4][4];
    #pragma unroll
    for (int i = 0; i < 4; i++)
        #pragma unroll
        for (int j = 0; j < 4; j++)
            #pragma unroll
            for (int u = 0; u < 4; u++) acc[i][j][u] = 0.f;

    int nIter = K / 16;

    // prologue: load tile 0 into buf 0
    {
        int r0 = ac0 >> 2, kc0 = (ac0 & 3) * 4;
        int r1 = ac1 >> 2, kc1 = (ac1 & 3) * 4;
        cpa16(&As[0][r0][kc0], A + (rowBase + r0)*lda + kc0);
        cpa16(&As[0][r1][kc1], A + (rowBase + r1)*lda + kc1);
        int br0 = ac0 >> 5, bn0 = (ac0 & 31) * 4;
        int br1 = ac1 >> 5, bn1 = (ac1 & 31) * 4;
        cpa16(&Bs[0][br0][bn0], Bw + (size_t)br0*ldb + colBase + bn0);
        cpa16(&Bs[0][br1][bn1], Bw + (size_t)br1*ldb + colBase + bn1);
        asm volatile("cp.async.commit_group;");
    }

    int buf = 0;
    for (int it = 0; it < nIter; it++) {
        asm volatile("cp.async.wait_group 0;");
        __syncthreads();

        if (it + 1 < nIter) {
            int k0 = (it + 1) * 16;
            int nb = buf ^ 1;
            int r0 = ac0 >> 2, kc0 = (ac0 & 3) * 4;
            int r1 = ac1 >> 2, kc1 = (ac1 & 3) * 4;
            cpa16(&As[nb][r0][kc0], A + (rowBase + r0)*lda + k0 + kc0);
            cpa16(&As[nb][r1][kc1], A + (rowBase + r1)*lda + k0 + kc1);
            int br0 = ac0 >> 5, bn0 = (ac0 & 31) * 4;
            int br1 = ac1 >> 5, bn1 = (ac1 & 31) * 4;
            cpa16(&Bs[nb][br0][bn0], Bw + (size_t)(k0+br0)*ldb + colBase + bn0);
            cpa16(&Bs[nb][br1][bn1], Bw + (size_t)(k0+br1)*ldb + colBase + bn1);
            asm volatile("cp.async.commit_group;");
        }

        #pragma unroll
        for (int kk = 0; kk < 16; kk += 8) {
            unsigned af[4][4], bf[4][2];
            #pragma unroll
            for (int mt = 0; mt < 4; mt++) {
                int m0 = wm + mt*16 + lr;
                af[mt][0] = f2tf(As[buf][m0    ][kk + lc]);
                af[mt][1] = f2tf(As[buf][m0 + 8][kk + lc]);
                af[mt][2] = f2tf(As[buf][m0    ][kk + lc + 4]);
                af[mt][3] = f2tf(As[buf][m0 + 8][kk + lc + 4]);
            }
            #pragma unroll
            for (int nt = 0; nt < 4; nt++) {
                int n0 = wn + nt*8 + lr;
                bf[nt][0] = f2tf(Bs[buf][kk + lc    ][n0]);
                bf[nt][1] = f2tf(Bs[buf][kk + lc + 4][n0]);
            }
            #pragma unroll
            for (int mt = 0; mt < 4; mt++)
                #pragma unroll
                for (int nt = 0; nt < 4; nt++)
                    mma_tf32(acc[mt][nt], af[mt], bf[nt]);
        }
        buf ^= 1;
    }

    // epilogue
    #pragma unroll
    for (int mt = 0; mt < 4; mt++) {
        size_t row0 = rowBase + wm + mt*16 + lr;
        #pragma unroll
        for (int nt = 0; nt < 4; nt++) {
            int col = colBase + wn + nt*8 + lc*2;
            float b0 = bias[col], b1 = bias[col+1];
            float a00=0.f,a01=0.f,a10=0.f,a11=0.f;
            if (addsrc) {
                const float* p0 = addsrc + row0*(size_t)ldadd + col;
                const float* p1 = addsrc + (row0+8)*(size_t)ldadd + col;
                a00 = p0[0]; a01 = p0[1]; a10 = p1[0]; a11 = p1[1];
            }
            float2 r0 = make_float2(acc[mt][nt][0] + b0 + a00, acc[mt][nt][1] + b1 + a01);
            float2 r1 = make_float2(acc[mt][nt][2] + b0 + a10, acc[mt][nt][3] + b1 + a11);
            *(float2*)(C + row0*(size_t)ldc + col)     = r0;
            *(float2*)(C + (row0+8)*(size_t)ldc + col) = r1;
        }
    }
}

// ---------------- gated scan ----------------
__global__ void scan_summ()
{
    int bc = blockIdx.x;               // 0..511
    int b = bc >> 6, c = bc & 63;
    int sd = threadIdx.x;
    size_t base = ((size_t)(b*TT + c*CHK))*N1 + sd;
    float ca = 1.f, wb = 0.f;
    for (int k = 0; k < CHK; k++) {
        float zg = g_Z[base + (size_t)k*N1];
        float zi = g_Z[base + (size_t)k*N1 + SDIM];
        float a = sigm(zg);
        float bb = (1.f - a)*zi;
        ca *= a;
        wb += bb / fmaxf(ca, 1e-8f);
    }
    int idx = bc*SDIM + sd;
    g_sumA[idx] = ca; g_sumB[idx] = wb;
}

__global__ void scan_carry()
{
    int b = blockIdx.x;
    int sd = threadIdx.x;
    float h = 0.f;
    for (int c = 0; c < NCH; c++) {
        int idx = (b*NCH + c)*SDIM + sd;
        g_hpr[idx] = h;
        h = g_sumA[idx]*(h + g_sumB[idx]);
    }
}

__global__ void scan_states()
{
    int bc = blockIdx.x;
    int b = bc >> 6, c = bc & 63;
    int sd = threadIdx.x;
    size_t zb = ((size_t)(b*TT + c*CHK))*N1 + sd;
    size_t ob = ((size_t)(b*TT + c*CHK))*KC2 + sd;
    float h = g_hpr[bc*SDIM + sd];
    float ca = 1.f, wb = 0.f;
    for (int k = 0; k < CHK; k++) {
        float zg = g_Z[zb + (size_t)k*N1];
        float zi = g_Z[zb + (size_t)k*N1 + SDIM];
        float a = sigm(zg);
        float bb = (1.f - a)*zi;
        ca *= a;
        wb += bb / fmaxf(ca, 1e-8f);
        g_A2[ob + (size_t)k*KC2] = ca*(h + wb);
    }
}

// ---------------- binding scan ----------------
__global__ void bind_chunksum()
{
    __shared__ float Vs[CB*ODIM];
    __shared__ float Ks[CB*ODIM];
    int b = blockIdx.x >> 5, c = blockIdx.x & 31;
    int tid = threadIdx.x;
    int j = tid >> 2, q0 = (tid & 3)*16;
    size_t zrow = ((size_t)(b*TT + c*CB + j))*N1;
    #pragma unroll
    for (int u = 0; u < 4; u++) {
        float4 vv = *(const float4*)&g_Z[zrow + 512 + q0 + u*4];
        float4 pp = *(const float4*)&g_pw[(63-j)*ODIM + q0 + u*4];
        vv.x *= pp.x; vv.y *= pp.y; vv.z *= pp.z; vv.w *= pp.w;
        *(float4*)&Vs[j*ODIM + q0 + u*4] = vv;
        float4 kk = *(const float4*)&g_Z[zrow + 576 + q0 + u*4];
        *(float4*)&Ks[j*ODIM + q0 + u*4] = kk;
    }
    __syncthreads();
    int i = tid >> 2, l0 = (tid & 3)*16;
    float acc[16] = {};
    for (int jj = 0; jj < CB; jj++) {
        float vv = Vs[jj*ODIM + i];
        #pragma unroll
        for (int u = 0; u < 16; u += 4) {
            float4 k4 = *(const float4*)&Ks[jj*ODIM + l0 + u];
            acc[u+0] += vv*k4.x; acc[u+1] += vv*k4.y;
            acc[u+2] += vv*k4.z; acc[u+3] += vv*k4.w;
        }
    }
    size_t mb = ((size_t)(b*NCB + c))*ODIM*ODIM + i*ODIM + l0;
    #pragma unroll
    for (int u = 0; u < 16; u += 4)
        *(float4*)&g_Mc[mb + u] = make_float4(acc[u], acc[u+1], acc[u+2], acc[u+3]);
}

__global__ void bind_carry()
{
    int gid = blockIdx.x*blockDim.x + threadIdx.x;   // 32768 lanes
    int b = gid >> 12, e = gid & 4095, i = e >> 6;
    float p64 = g_pw[64*ODIM + i];
    float s = 0.f;
    size_t base = (size_t)b*NCB*4096 + e;
    for (int c = 0; c < NCB; c++) {
        g_Sc[base + (size_t)c*4096] = s;
        s = p64*s + g_Mc[base + (size_t)c*4096];
    }
}

__global__ void bind_out()
{
    extern __shared__ float sm[];
    float* Qs  = sm;            // [64][65]  Q[t][l]
    float* KT  = sm + 4160;     // [64][64]  K^T[l][j] -> later Cq[t][i]
    float* SV  = sm + 8256;     // [64][64]  S^T[l][i] -> later V[j][i]
    float* As  = sm + 12352;    // [64][65]  A[t][j]
    float* pws = sm + 16512;    // [65][64]
    int b = blockIdx.x >> 5, c = blockIdx.x & 31;
    int tid = threadIdx.x;
    int t = tid >> 2, q0 = (tid & 3)*16;
    size_t zrow = ((size_t)(b*TT + c*CB + t))*N1;
    size_t srow = ((size_t)(b*NCB + c))*4096 + t*ODIM;
    #pragma unroll
    for (int u = 0; u < 4; u++) {
        float4 qv = *(const float4*)&g_Z[zrow + 640 + q0 + u*4];
        Qs[t*65 + q0+u*4+0] = qv.x; Qs[t*65 + q0+u*4+1] = qv.y;
        Qs[t*65 + q0+u*4+2] = qv.z; Qs[t*65 + q0+u*4+3] = qv.w;
        float4 kv = *(const float4*)&g_Z[zrow + 576 + q0 + u*4];     // t plays "j"
        KT[(q0+u*4+0)*ODIM + t] = kv.x; KT[(q0+u*4+1)*ODIM + t] = kv.y;
        KT[(q0+u*4+2)*ODIM + t] = kv.z; KT[(q0+u*4+3)*ODIM + t] = kv.w;
        float4 sv = *(const float4*)&g_Sc[srow + q0 + u*4];          // t plays "i"
        SV[(q0+u*4+0)*ODIM + t] = sv.x; SV[(q0+u*4+1)*ODIM + t] = sv.y;
        SV[(q0+u*4+2)*ODIM + t] = sv.z; SV[(q0+u*4+3)*ODIM + t] = sv.w;
    }
    for (int idx = tid; idx < 65*ODIM; idx += 256) pws[idx] = g_pw[idx];
    __syncthreads();

    float accA[16] = {}, accC[16] = {};
    for (int l = 0; l < ODIM; l++) {
        float q = Qs[t*65 + l];
        #pragma unroll
        for (int u = 0; u < 16; u += 4) {
            float4 k4 = *(const float4*)&KT[l*ODIM + q0 + u];
            float4 s4 = *(const float4*)&SV[l*ODIM + q0 + u];
            accA[u+0] += q*k4.x; accA[u+1] += q*k4.y; accA[u+2] += q*k4.z; accA[u+3] += q*k4.w;
            accC[u+0] += q*s4.x; accC[u+1] += q*s4.y; accC[u+2] += q*s4.z; accC[u+3] += q*s4.w;
        }
    }
    __syncthreads();
    #pragma unroll
    for (int u = 0; u < 16; u++) As[t*65 + q0 + u] = accA[u];
    #pragma unroll
    for (int u = 0; u < 16; u += 4)
        *(float4*)&KT[t*ODIM + q0 + u] = make_float4(accC[u], accC[u+1], accC[u+2], accC[u+3]);
    #pragma unroll
    for (int u = 0; u < 4; u++) {
        float4 vv = *(const float4*)&g_Z[zrow + 512 + q0 + u*4];     // t plays "j"
        *(float4*)&SV[t*ODIM + q0 + u*4] = vv;
    }
    __syncthreads();

    float o[16];
    #pragma unroll
    for (int u = 0; u < 16; u++)
        o[u] = pws[(t+1)*ODIM + q0 + u] * KT[t*ODIM + q0 + u];
    for (int j = 0; j <= t; j++) {
        float a = As[t*65 + j];
        int d = t - j;
        #pragma unroll
        for (int u = 0; u < 16; u += 4) {
            float4 p4 = *(const float4*)&pws[d*ODIM + q0 + u];
            float4 v4 = *(const float4*)&SV[j*ODIM + q0 + u];
            o[u+0] += a*p4.x*v4.x; o[u+1] += a*p4.y*v4.y;
            o[u+2] += a*p4.z*v4.z; o[u+3] += a*p4.w*v4.w;
        }
    }
    size_t orow = ((size_t)(b*TT + c*CB + t))*KC2 + SDIM + q0;
    #pragma unroll
    for (int u = 0; u < 16; u += 4)
        *(float4*)&g_A2[orow + u] = make_float4(o[u], o[u+1], o[u+2], o[u+3]);
}

// ---------------- layernorm: warp per row ----------------
__global__ void ln_kernel(const float* __restrict__ lng, const float* __restrict__ lnb,
                          float* __restrict__ out)
{
    int row = blockIdx.x*8 + (threadIdx.x >> 5);
    int lane = threadIdx.x & 31;
    const float4* y4 = (const float4*)(g_Y + (size_t)row*DD);
    float4 v[4];
    float s = 0.f, s2 = 0.f;
    #pragma unroll
    for (int u = 0; u < 4; u++) {
        v[u] = y4[lane + u*32];
        s  += v[u].x + v[u].y + v[u].z + v[u].w;
        s2 += v[u].x*v[u].x + v[u].y*v[u].y + v[u].z*v[u].z + v[u].w*v[u].w;
    }
    #pragma unroll
    for (int off = 16; off; off >>= 1) {
        s  += __shfl_xor_sync(0xffffffffu, s,  off);
        s2 += __shfl_xor_sync(0xffffffffu, s2, off);
    }
    float mu  = s * (1.f/512.f);
    float var = s2 * (1.f/512.f) - mu*mu;
    float inv = rsqrtf(var + 1e-5f);
    float4* o4 = (float4*)(out + (size_t)row*DD);
    const float4* g4 = (const float4*)lng;
    const float4* b4 = (const float4*)lnb;
    #pragma unroll
    for (int u = 0; u < 4; u++) {
        float4 gg = g4[lane + u*32];
        float4 bb = b4[lane + u*32];
        float4 r;
        r.x = (v[u].x - mu)*inv*gg.x + bb.x;
        r.y = (v[u].y - mu)*inv*gg.y + bb.y;
        r.z = (v[u].z - mu)*inv*gg.z + bb.z;
        r.w = (v[u].w - mu)*inv*gg.w + bb.w;
        o4[lane + u*32] = r;
    }
}

// ---------------- host launch ----------------
extern "C" void kernel_launch(void* const* d_in, const int* in_sizes, int n_in,
                              void* d_out, int out_size)
{
    const float* x       = (const float*)d_in[0];
    const float* gate_W  = (const float*)d_in[1];
    const float* gate_b  = (const float*)d_in[2];
    const float* in_W    = (const float*)d_in[3];
    const float* in_b    = (const float*)d_in[4];
    const float* out_W   = (const float*)d_in[5];
    const float* out_b   = (const float*)d_in[6];
    const float* opv_W   = (const float*)d_in[7];
    const float* opv_b   = (const float*)d_in[8];
    const float* opk_W   = (const float*)d_in[9];
    const float* opk_b   = (const float*)d_in[10];
    const float* opq_W   = (const float*)d_in[11];
    const float* opq_b   = (const float*)d_in[12];
    const float* op_decay= (const float*)d_in[13];
    const float* opout_W = (const float*)d_in[14];
    const float* opout_b = (const float*)d_in[15];
    const float* ln_g    = (const float*)d_in[16];
    const float* ln_b    = (const float*)d_in[17];
    float* out = (float*)d_out;

    void *pW1, *pb1, *pZ, *pW2, *pb2, *pA2, *pY;
    cudaGetSymbolAddress(&pW1, g_W1);
    cudaGetSymbolAddress(&pb1, g_b1);
    cudaGetSymbolAddress(&pZ,  g_Z);
    cudaGetSymbolAddress(&pW2, g_W2);
    cudaGetSymbolAddress(&pb2, g_b2);
    cudaGetSymbolAddress(&pA2, g_A2);
    cudaGetSymbolAddress(&pY,  g_Y);

    cudaFuncSetAttribute(bind_out, cudaFuncAttributeMaxDynamicSharedMemorySize, 20672*4);

    // prep
    pack_w1<<<(DD*N1 + 255)/256, 256>>>(gate_W, gate_b, in_W, in_b,
                                        opv_W, opv_b, opk_W, opk_b, opq_W, opq_b);
    pack_w2<<<(KC2*DD + 255)/256, 256>>>(out_W, out_b, opout_W, opout_b);
    pw_kernel<<<1, 64>>>(op_decay);

    // GEMM-1: Z = x @ W1 + b1   (tf32 tensor cores)
    gemm_tf32<<<dim3(N1/128, MM/128), 256>>>(
        x, DD, (const float*)pW1, N1, (const float*)pb1,
        nullptr, 0, (float*)pZ, N1, DD);

    // gated scan
    scan_summ<<<BQ*NCH, SDIM>>>();
    scan_carry<<<BQ, SDIM>>>();
    scan_states<<<BQ*NCH, SDIM>>>();

    // binding scan
    bind_chunksum<<<BQ*NCB, 256>>>();
    bind_carry<<<BQ*NCB*16/32, 256>>>();      // 32768 lanes / 256
    bind_out<<<BQ*NCB, 256, 20672*4>>>();

    // GEMM-2: Y = A2 @ W2 + b2 + x   (tf32 tensor cores)
    gemm_tf32<<<dim3(DD/128, MM/128), 256>>>(
        (const float*)pA2, KC2, (const float*)pW2, DD, (const float*)pb2,
        x, DD, (float*)pY, DD, KC2);

    // layernorm -> out
    ln_kernel<<<MM/8, 256>>>(ln_g, ln_b, out);
}

// round 4
// speedup vs baseline: 1.9332x; 1.0572x over previous
#include <cuda_runtime.h>
#include <math.h>

// Problem constants
#define BQ 8
#define TT 2048
#define DD 512
#define SDIM 256
#define ODIM 64
#define MM (BQ*TT)          // 16384 rows
#define N1 768              // padded 704 (gate 0-255 | in 256-511 | v 512-575 | k 576-639 | q 640-703)
#define KC2 320             // states(256) + bind(64)
#define NCH 64              // scan chunks of 32
#define CHK 32
#define CB 64               // binding chunk
#define NCB 32

// ---------------- device scratch (no runtime allocation) ----------------
__device__ float g_W1[DD*N1];
__device__ float g_b1[N1];
__device__ float g_Xc[(size_t)MM*DD];     // tf32-rounded copy of x
__device__ float g_Z[(size_t)MM*N1];
__device__ float g_W2[KC2*DD];
__device__ float g_b2[DD];
__device__ float g_A2[(size_t)MM*KC2];    // written pre-rounded to tf32
__device__ float g_Y[(size_t)MM*DD];
__device__ float g_sumA[BQ*NCH*SDIM];
__device__ float g_sumB[BQ*NCH*SDIM];
__device__ float g_hpr[BQ*NCH*SDIM];
__device__ float g_Mc[(size_t)BQ*NCB*ODIM*ODIM];
__device__ float g_Sc[(size_t)BQ*NCB*ODIM*ODIM];
__device__ float g_pw[65*ODIM];

__device__ __forceinline__ float sigm_acc(float z){ return 1.0f/(1.0f+expf(-z)); }
__device__ __forceinline__ float sigm(float z){ return 1.0f/(1.0f+__expf(-z)); }

__device__ __forceinline__ unsigned f2tf(float x){
    unsigned r; asm("cvt.rna.tf32.f32 %0, %1;" : "=r"(r) : "f"(x)); return r;
}
__device__ __forceinline__ float tfr(float x){ return __uint_as_float(f2tf(x)); }

// ---------------- prep kernels ----------------
__global__ void pack_w1(const float* __restrict__ gW, const float* __restrict__ gb,
                        const float* __restrict__ iW, const float* __restrict__ ib,
                        const float* __restrict__ vW, const float* __restrict__ vb,
                        const float* __restrict__ kW, const float* __restrict__ kb,
                        const float* __restrict__ qW, const float* __restrict__ qb)
{
    int idx = blockIdx.x*256 + threadIdx.x;
    if (idx < DD*N1) {
        int d = idx / N1, n = idx % N1;
        float w = 0.f;
        if      (n < 256) w = gW[d*256 + n];
        else if (n < 512) w = iW[d*256 + (n-256)];
        else if (n < 576) w = vW[d*64 + (n-512)];
        else if (n < 640) w = kW[d*64 + (n-576)];
        else if (n < 704) w = qW[d*64 + (n-640)];
        g_W1[idx] = tfr(w);
    }
    if (idx < N1) {
        float b = 0.f;
        if      (idx < 256) b = gb[idx];
        else if (idx < 512) b = ib[idx-256];
        else if (idx < 576) b = vb[idx-512];
        else if (idx < 640) b = kb[idx-576];
        else if (idx < 704) b = qb[idx-640];
        g_b1[idx] = b;
    }
}

__global__ void pack_w2(const float* __restrict__ oW, const float* __restrict__ ob,
                        const float* __restrict__ pW, const float* __restrict__ pb)
{
    int idx = blockIdx.x*256 + threadIdx.x;
    if (idx < KC2*DD) {
        int r = idx / DD, c = idx % DD;
        g_W2[idx] = tfr((r < 256) ? oW[r*DD + c] : pW[(r-256)*DD + c]);
    }
    if (idx < DD) g_b2[idx] = ob[idx] + pb[idx];
}

// tf32-round x into g_Xc (float4 per thread)
__global__ void cvt_x(const float* __restrict__ x)
{
    size_t i4 = (size_t)blockIdx.x*256 + threadIdx.x;
    float4 v = ((const float4*)x)[i4];
    v.x = tfr(v.x); v.y = tfr(v.y); v.z = tfr(v.z); v.w = tfr(v.w);
    ((float4*)g_Xc)[i4] = v;
}

__global__ void pw_kernel(const float* __restrict__ op_decay)
{
    int i = threadIdx.x;
    if (i < ODIM) {
        float d = sigm_acc(op_decay[i]);
        float p = 1.f;
        for (int e = 0; e <= 64; e++) { g_pw[e*ODIM + i] = p; p *= d; }
    }
}

// ---------------- tf32 tensor-core GEMM (operands pre-rounded) ----------------
#define ASTRIDE 20
#define BSTRIDE 136

__device__ __forceinline__ void mma_tf32(float* c, const unsigned* a, const unsigned* b){
    asm volatile(
      "mma.sync.aligned.m16n8k8.row.col.f32.tf32.tf32.f32 "
      "{%0,%1,%2,%3}, {%4,%5,%6,%7}, {%8,%9}, {%0,%1,%2,%3};\n"
      : "+f"(c[0]), "+f"(c[1]), "+f"(c[2]), "+f"(c[3])
      : "r"(a[0]), "r"(a[1]), "r"(a[2]), "r"(a[3]), "r"(b[0]), "r"(b[1]));
}
__device__ __forceinline__ void cpa16(void* dst, const void* src){
    unsigned d = (unsigned)__cvta_generic_to_shared(dst);
    asm volatile("cp.async.cg.shared.global [%0], [%1], 16;" :: "r"(d), "l"(src));
}

__global__ void __launch_bounds__(256,2) gemm_tf32(
    const float* __restrict__ A, int lda,
    const float* __restrict__ Bw, int ldb,
    const float* __restrict__ bias,
    const float* __restrict__ addsrc, int ldadd,
    float* __restrict__ C, int ldc, int K)
{
    __shared__ float As[2][128][ASTRIDE];   // [m][k] padded
    __shared__ float Bs[2][16][BSTRIDE];    // [k][n] padded

    int tid  = threadIdx.x;
    int lane = tid & 31, warp = tid >> 5;
    int wm = (warp >> 2) * 64;      // warp m offset (0/64)
    int wn = (warp & 3) * 32;       // warp n offset (0..96)
    int lr = lane >> 2;             // 0..7
    int lc = lane & 3;              // 0..3

    size_t rowBase = (size_t)blockIdx.y * 128;
    int colBase = blockIdx.x * 128;

    int ac0 = tid, ac1 = tid + 256;

    float acc[4][4][4];
    #pragma unroll
    for (int i = 0; i < 4; i++)
        #pragma unroll
        for (int j = 0; j < 4; j++)
            #pragma unroll
            for (int u = 0; u < 4; u++) acc[i][j][u] = 0.f;

    int nIter = K / 16;

    {
        int r0 = ac0 >> 2, kc0 = (ac0 & 3) * 4;
        int r1 = ac1 >> 2, kc1 = (ac1 & 3) * 4;
        cpa16(&As[0][r0][kc0], A + (rowBase + r0)*lda + kc0);
        cpa16(&As[0][r1][kc1], A + (rowBase + r1)*lda + kc1);
        int br0 = ac0 >> 5, bn0 = (ac0 & 31) * 4;
        int br1 = ac1 >> 5, bn1 = (ac1 & 31) * 4;
        cpa16(&Bs[0][br0][bn0], Bw + (size_t)br0*ldb + colBase + bn0);
        cpa16(&Bs[0][br1][bn1], Bw + (size_t)br1*ldb + colBase + bn1);
        asm volatile("cp.async.commit_group;");
    }

    int buf = 0;
    for (int it = 0; it < nIter; it++) {
        asm volatile("cp.async.wait_group 0;");
        __syncthreads();

        if (it + 1 < nIter) {
            int k0 = (it + 1) * 16;
            int nb = buf ^ 1;
            int r0 = ac0 >> 2, kc0 = (ac0 & 3) * 4;
            int r1 = ac1 >> 2, kc1 = (ac1 & 3) * 4;
            cpa16(&As[nb][r0][kc0], A + (rowBase + r0)*lda + k0 + kc0);
            cpa16(&As[nb][r1][kc1], A + (rowBase + r1)*lda + k0 + kc1);
            int br0 = ac0 >> 5, bn0 = (ac0 & 31) * 4;
            int br1 = ac1 >> 5, bn1 = (ac1 & 31) * 4;
            cpa16(&Bs[nb][br0][bn0], Bw + (size_t)(k0+br0)*ldb + colBase + bn0);
            cpa16(&Bs[nb][br1][bn1], Bw + (size_t)(k0+br1)*ldb + colBase + bn1);
            asm volatile("cp.async.commit_group;");
        }

        #pragma unroll
        for (int kk = 0; kk < 16; kk += 8) {
            unsigned af[4][4], bf[4][2];
            #pragma unroll
            for (int mt = 0; mt < 4; mt++) {
                int m0 = wm + mt*16 + lr;
                af[mt][0] = __float_as_uint(As[buf][m0    ][kk + lc]);
                af[mt][1] = __float_as_uint(As[buf][m0 + 8][kk + lc]);
                af[mt][2] = __float_as_uint(As[buf][m0    ][kk + lc + 4]);
                af[mt][3] = __float_as_uint(As[buf][m0 + 8][kk + lc + 4]);
            }
            #pragma unroll
            for (int nt = 0; nt < 4; nt++) {
                int n0 = wn + nt*8 + lr;
                bf[nt][0] = __float_as_uint(Bs[buf][kk + lc    ][n0]);
                bf[nt][1] = __float_as_uint(Bs[buf][kk + lc + 4][n0]);
            }
            #pragma unroll
            for (int mt = 0; mt < 4; mt++)
                #pragma unroll
                for (int nt = 0; nt < 4; nt++)
                    mma_tf32(acc[mt][nt], af[mt], bf[nt]);
        }
        buf ^= 1;
    }

    // epilogue
    #pragma unroll
    for (int mt = 0; mt < 4; mt++) {
        size_t row0 = rowBase + wm + mt*16 + lr;
        #pragma unroll
        for (int nt = 0; nt < 4; nt++) {
            int col = colBase + wn + nt*8 + lc*2;
            float b0 = bias[col], b1 = bias[col+1];
            float a00=0.f,a01=0.f,a10=0.f,a11=0.f;
            if (addsrc) {
                const float* p0 = addsrc + row0*(size_t)ldadd + col;
                const float* p1 = addsrc + (row0+8)*(size_t)ldadd + col;
                a00 = p0[0]; a01 = p0[1]; a10 = p1[0]; a11 = p1[1];
            }
            float2 r0 = make_float2(acc[mt][nt][0] + b0 + a00, acc[mt][nt][1] + b1 + a01);
            float2 r1 = make_float2(acc[mt][nt][2] + b0 + a10, acc[mt][nt][3] + b1 + a11);
            *(float2*)(C + row0*(size_t)ldc + col)     = r0;
            *(float2*)(C + (row0+8)*(size_t)ldc + col) = r1;
        }
    }
}

// ---------------- gated scan ----------------
__global__ void scan_summ()
{
    int bc = blockIdx.x;               // 0..511
    int b = bc >> 6, c = bc & 63;
    int sd = threadIdx.x;
    size_t base = ((size_t)(b*TT + c*CHK))*N1 + sd;
    float ca = 1.f, wb = 0.f;
    for (int k = 0; k < CHK; k++) {
        float zg = g_Z[base + (size_t)k*N1];
        float zi = g_Z[base + (size_t)k*N1 + SDIM];
        float a = sigm(zg);
        float bb = (1.f - a)*zi;
        ca *= a;
        wb += bb / fmaxf(ca, 1e-8f);
    }
    int idx = bc*SDIM + sd;
    g_sumA[idx] = ca; g_sumB[idx] = wb;
}

__global__ void scan_carry()
{
    int b = blockIdx.x;
    int sd = threadIdx.x;
    float h = 0.f;
    for (int c = 0; c < NCH; c++) {
        int idx = (b*NCH + c)*SDIM + sd;
        g_hpr[idx] = h;
        h = g_sumA[idx]*(h + g_sumB[idx]);
    }
}

__global__ void scan_states()
{
    int bc = blockIdx.x;
    int b = bc >> 6, c = bc & 63;
    int sd = threadIdx.x;
    size_t zb = ((size_t)(b*TT + c*CHK))*N1 + sd;
    size_t ob = ((size_t)(b*TT + c*CHK))*KC2 + sd;
    float h = g_hpr[bc*SDIM + sd];
    float ca = 1.f, wb = 0.f;
    for (int k = 0; k < CHK; k++) {
        float zg = g_Z[zb + (size_t)k*N1];
        float zi = g_Z[zb + (size_t)k*N1 + SDIM];
        float a = sigm(zg);
        float bb = (1.f - a)*zi;
        ca *= a;
        wb += bb / fmaxf(ca, 1e-8f);
        g_A2[ob + (size_t)k*KC2] = tfr(ca*(h + wb));
    }
}

// ---------------- binding scan ----------------
__global__ void bind_chunksum()
{
    __shared__ float Vs[CB*ODIM];
    __shared__ float Ks[CB*ODIM];
    int b = blockIdx.x >> 5, c = blockIdx.x & 31;
    int tid = threadIdx.x;
    int j = tid >> 2, q0 = (tid & 3)*16;
    size_t zrow = ((size_t)(b*TT + c*CB + j))*N1;
    #pragma unroll
    for (int u = 0; u < 4; u++) {
        float4 vv = *(const float4*)&g_Z[zrow + 512 + q0 + u*4];
        float4 pp = *(const float4*)&g_pw[(63-j)*ODIM + q0 + u*4];
        vv.x *= pp.x; vv.y *= pp.y; vv.z *= pp.z; vv.w *= pp.w;
        *(float4*)&Vs[j*ODIM + q0 + u*4] = vv;
        float4 kk = *(const float4*)&g_Z[zrow + 576 + q0 + u*4];
        *(float4*)&Ks[j*ODIM + q0 + u*4] = kk;
    }
    __syncthreads();
    int i = tid >> 2, l0 = (tid & 3)*16;
    float acc[16] = {};
    for (int jj = 0; jj < CB; jj++) {
        float vv = Vs[jj*ODIM + i];
        #pragma unroll
        for (int u = 0; u < 16; u += 4) {
            float4 k4 = *(const float4*)&Ks[jj*ODIM + l0 + u];
            acc[u+0] += vv*k4.x; acc[u+1] += vv*k4.y;
            acc[u+2] += vv*k4.z; acc[u+3] += vv*k4.w;
        }
    }
    size_t mb = ((size_t)(b*NCB + c))*ODIM*ODIM + i*ODIM + l0;
    #pragma unroll
    for (int u = 0; u < 16; u += 4)
        *(float4*)&g_Mc[mb + u] = make_float4(acc[u], acc[u+1], acc[u+2], acc[u+3]);
}

__global__ void bind_carry()
{
    int gid = blockIdx.x*blockDim.x + threadIdx.x;   // 32768 lanes
    int b = gid >> 12, e = gid & 4095, i = e >> 6;
    float p64 = g_pw[64*ODIM + i];
    float s = 0.f;
    size_t base = (size_t)b*NCB*4096 + e;
    for (int c = 0; c < NCB; c++) {
        g_Sc[base + (size_t)c*4096] = s;
        s = p64*s + g_Mc[base + (size_t)c*4096];
    }
}

__global__ void bind_out()
{
    extern __shared__ float sm[];
    float* Qs  = sm;            // [64][65]  Q[t][l]
    float* KT  = sm + 4160;     // [64][64]  K^T[l][j] -> later Cq[t][i]
    float* SV  = sm + 8256;     // [64][64]  S^T[l][i] -> later V[j][i]
    float* As  = sm + 12352;    // [64][65]  A[t][j]
    float* pws = sm + 16512;    // [65][64]
    int b = blockIdx.x >> 5, c = blockIdx.x & 31;
    int tid = threadIdx.x;
    int t = tid >> 2, q0 = (tid & 3)*16;
    size_t zrow = ((size_t)(b*TT + c*CB + t))*N1;
    size_t srow = ((size_t)(b*NCB + c))*4096 + t*ODIM;
    #pragma unroll
    for (int u = 0; u < 4; u++) {
        float4 qv = *(const float4*)&g_Z[zrow + 640 + q0 + u*4];
        Qs[t*65 + q0+u*4+0] = qv.x; Qs[t*65 + q0+u*4+1] = qv.y;
        Qs[t*65 + q0+u*4+2] = qv.z; Qs[t*65 + q0+u*4+3] = qv.w;
        float4 kv = *(const float4*)&g_Z[zrow + 576 + q0 + u*4];     // t plays "j"
        KT[(q0+u*4+0)*ODIM + t] = kv.x; KT[(q0+u*4+1)*ODIM + t] = kv.y;
        KT[(q0+u*4+2)*ODIM + t] = kv.z; KT[(q0+u*4+3)*ODIM + t] = kv.w;
        float4 sv = *(const float4*)&g_Sc[srow + q0 + u*4];          // t plays "i"
        SV[(q0+u*4+0)*ODIM + t] = sv.x; SV[(q0+u*4+1)*ODIM + t] = sv.y;
        SV[(q0+u*4+2)*ODIM + t] = sv.z; SV[(q0+u*4+3)*ODIM + t] = sv.w;
    }
    for (int idx = tid; idx < 65*ODIM; idx += 256) pws[idx] = g_pw[idx];
    __syncthreads();

    float accA[16] = {}, accC[16] = {};
    for (int l = 0; l < ODIM; l++) {
        float q = Qs[t*65 + l];
        #pragma unroll
        for (int u = 0; u < 16; u += 4) {
            float4 k4 = *(const float4*)&KT[l*ODIM + q0 + u];
            float4 s4 = *(const float4*)&SV[l*ODIM + q0 + u];
            accA[u+0] += q*k4.x; accA[u+1] += q*k4.y; accA[u+2] += q*k4.z; accA[u+3] += q*k4.w;
            accC[u+0] += q*s4.x; accC[u+1] += q*s4.y; accC[u+2] += q*s4.z; accC[u+3] += q*s4.w;
        }
    }
    __syncthreads();
    #pragma unroll
    for (int u = 0; u < 16; u++) As[t*65 + q0 + u] = accA[u];
    #pragma unroll
    for (int u = 0; u < 16; u += 4)
        *(float4*)&KT[t*ODIM + q0 + u] = make_float4(accC[u], accC[u+1], accC[u+2], accC[u+3]);
    #pragma unroll
    for (int u = 0; u < 4; u++) {
        float4 vv = *(const float4*)&g_Z[zrow + 512 + q0 + u*4];     // t plays "j"
        *(float4*)&SV[t*ODIM + q0 + u*4] = vv;
    }
    __syncthreads();

    float o[16];
    #pragma unroll
    for (int u = 0; u < 16; u++)
        o[u] = pws[(t+1)*ODIM + q0 + u] * KT[t*ODIM + q0 + u];
    for (int j = 0; j <= t; j++) {
        float a = As[t*65 + j];
        int d = t - j;
        #pragma unroll
        for (int u = 0; u < 16; u += 4) {
            float4 p4 = *(const float4*)&pws[d*ODIM + q0 + u];
            float4 v4 = *(const float4*)&SV[j*ODIM + q0 + u];
            o[u+0] += a*p4.x*v4.x; o[u+1] += a*p4.y*v4.y;
            o[u+2] += a*p4.z*v4.z; o[u+3] += a*p4.w*v4.w;
        }
    }
    size_t orow = ((size_t)(b*TT + c*CB + t))*KC2 + SDIM + q0;
    #pragma unroll
    for (int u = 0; u < 16; u += 4)
        *(float4*)&g_A2[orow + u] = make_float4(tfr(o[u]), tfr(o[u+1]), tfr(o[u+2]), tfr(o[u+3]));
}

// ---------------- layernorm: warp per row ----------------
__global__ void ln_kernel(const float* __restrict__ lng, const float* __restrict__ lnb,
                          float* __restrict__ out)
{
    int row = blockIdx.x*8 + (threadIdx.x >> 5);
    int lane = threadIdx.x & 31;
    const float4* y4 = (const float4*)(g_Y + (size_t)row*DD);
    float4 v[4];
    float s = 0.f, s2 = 0.f;
    #pragma unroll
    for (int u = 0; u < 4; u++) {
        v[u] = y4[lane + u*32];
        s  += v[u].x + v[u].y + v[u].z + v[u].w;
        s2 += v[u].x*v[u].x + v[u].y*v[u].y + v[u].z*v[u].z + v[u].w*v[u].w;
    }
    #pragma unroll
    for (int off = 16; off; off >>= 1) {
        s  += __shfl_xor_sync(0xffffffffu, s,  off);
        s2 += __shfl_xor_sync(0xffffffffu, s2, off);
    }
    float mu  = s * (1.f/512.f);
    float var = s2 * (1.f/512.f) - mu*mu;
    float inv = rsqrtf(var + 1e-5f);
    float4* o4 = (float4*)(out + (size_t)row*DD);
    const float4* g4 = (const float4*)lng;
    const float4* b4 = (const float4*)lnb;
    #pragma unroll
    for (int u = 0; u < 4; u++) {
        float4 gg = g4[lane + u*32];
        float4 bb = b4[lane + u*32];
        float4 r;
        r.x = (v[u].x - mu)*inv*gg.x + bb.x;
        r.y = (v[u].y - mu)*inv*gg.y + bb.y;
        r.z = (v[u].z - mu)*inv*gg.z + bb.z;
        r.w = (v[u].w - mu)*inv*gg.w + bb.w;
        o4[lane + u*32] = r;
    }
}

// ---------------- host launch ----------------
extern "C" void kernel_launch(void* const* d_in, const int* in_sizes, int n_in,
                              void* d_out, int out_size)
{
    const float* x       = (const float*)d_in[0];
    const float* gate_W  = (const float*)d_in[1];
    const float* gate_b  = (const float*)d_in[2];
    const float* in_W    = (const float*)d_in[3];
    const float* in_b    = (const float*)d_in[4];
    const float* out_W   = (const float*)d_in[5];
    const float* out_b   = (const float*)d_in[6];
    const float* opv_W   = (const float*)d_in[7];
    const float* opv_b   = (const float*)d_in[8];
    const float* opk_W   = (const float*)d_in[9];
    const float* opk_b   = (const float*)d_in[10];
    const float* opq_W   = (const float*)d_in[11];
    const float* opq_b   = (const float*)d_in[12];
    const float* op_decay= (const float*)d_in[13];
    const float* opout_W = (const float*)d_in[14];
    const float* opout_b = (const float*)d_in[15];
    const float* ln_g    = (const float*)d_in[16];
    const float* ln_b    = (const float*)d_in[17];
    float* out = (float*)d_out;

    void *pW1, *pb1, *pZ, *pW2, *pb2, *pA2, *pY, *pXc;
    cudaGetSymbolAddress(&pW1, g_W1);
    cudaGetSymbolAddress(&pb1, g_b1);
    cudaGetSymbolAddress(&pZ,  g_Z);
    cudaGetSymbolAddress(&pW2, g_W2);
    cudaGetSymbolAddress(&pb2, g_b2);
    cudaGetSymbolAddress(&pA2, g_A2);
    cudaGetSymbolAddress(&pY,  g_Y);
    cudaGetSymbolAddress(&pXc, g_Xc);

    cudaFuncSetAttribute(bind_out, cudaFuncAttributeMaxDynamicSharedMemorySize, 20672*4);

    // prep
    pack_w1<<<(DD*N1 + 255)/256, 256>>>(gate_W, gate_b, in_W, in_b,
                                        opv_W, opv_b, opk_W, opk_b, opq_W, opq_b);
    pack_w2<<<(KC2*DD + 255)/256, 256>>>(out_W, out_b, opout_W, opout_b);
    pw_kernel<<<1, 64>>>(op_decay);
    cvt_x<<<(MM*DD/4)/256, 256>>>(x);

    // GEMM-1: Z = Xc @ W1 + b1   (tf32 tensor cores, pre-rounded operands)
    gemm_tf32<<<dim3(N1/128, MM/128), 256>>>(
        (const float*)pXc, DD, (const float*)pW1, N1, (const float*)pb1,
        nullptr, 0, (float*)pZ, N1, DD);

    // gated scan
    scan_summ<<<BQ*NCH, SDIM>>>();
    scan_carry<<<BQ, SDIM>>>();
    scan_states<<<BQ*NCH, SDIM>>>();

    // binding scan
    bind_chunksum<<<BQ*NCB, 256>>>();
    bind_carry<<<BQ*NCB*16/32, 256>>>();      // 32768 lanes / 256
    bind_out<<<BQ*NCB, 256, 20672*4>>>();

    // GEMM-2: Y = A2 @ W2 + b2 + x   (tf32 tensor cores, pre-rounded operands)
    gemm_tf32<<<dim3(DD/128, MM/128), 256>>>(
        (const float*)pA2, KC2, (const float*)pW2, DD, (const float*)pb2,
        x, DD, (float*)pY, DD, KC2);

    // layernorm -> out
    ln_kernel<<<MM/8, 256>>>(ln_g, ln_b, out);
}